// round 14
// baseline (speedup 1.0000x reference)
#include <cuda_runtime.h>
#include <cuda_bf16.h>
#include <cstdint>

// PCEN, 10 smoother coefficients.
//   m[s,t] = (1-s)*m[s,t-1] + s*x[t],  m[s,0] = x[0]
//   out = (x*(EPS+m)^(-alpha) + delta)^r - delta^r
//
// R14: RPT=16 (16 t per lane, 512-t chunks, NCHUNK=4) halves the number of
// exposed Kogge-Stone scan phases per warp (the MUFU-idle windows) and the
// scan instruction overhead. Packed f32x2 epilogue (R13), CPW=2, sequential
// per-chain processing to bound register liveness, store-early.

#define PCEN_EPS 1e-5f
#define NS 10
#define CPW 2
#define NPAIR (NS / CPW)
#define TT 2048
#define RPT 16
#define CHUNK (32 * RPT)          // 512
#define NCHUNK (TT / CHUNK)       // 4

typedef unsigned long long u64;

__device__ __forceinline__ float fast_ex2(float v) {
    float r; asm("ex2.approx.ftz.f32 %0, %1;" : "=f"(r) : "f"(v)); return r;
}
__device__ __forceinline__ float fast_lg2(float v) {
    float r; asm("lg2.approx.ftz.f32 %0, %1;" : "=f"(r) : "f"(v)); return r;
}

// ---- f32x2 packed helpers ----
__device__ __forceinline__ u64 pk2(float lo, float hi) {
    u64 d;
    asm("mov.b64 %0, {%1, %2};" : "=l"(d)
        : "r"(__float_as_uint(lo)), "r"(__float_as_uint(hi)));
    return d;
}
__device__ __forceinline__ void upk2(u64 v, float& lo, float& hi) {
    uint32_t a, b;
    asm("mov.b64 {%0, %1}, %2;" : "=r"(a), "=r"(b) : "l"(v));
    lo = __uint_as_float(a); hi = __uint_as_float(b);
}
__device__ __forceinline__ u64 fma2(u64 a, u64 b, u64 c) {
    u64 d; asm("fma.rn.f32x2 %0, %1, %2, %3;" : "=l"(d) : "l"(a), "l"(b), "l"(c)); return d;
}
__device__ __forceinline__ u64 mul2(u64 a, u64 b) {
    u64 d; asm("mul.rn.f32x2 %0, %1, %2;" : "=l"(d) : "l"(a), "l"(b)); return d;
}
__device__ __forceinline__ u64 add2(u64 a, u64 b) {
    u64 d; asm("add.rn.f32x2 %0, %1, %2;" : "=l"(d) : "l"(a), "l"(b)); return d;
}

// packed-constant bit patterns
#define EPS2_C   0x3727C5AC3727C5ACULL   // 1e-5f
#define MAGIC2_C 0x4B4000004B400000ULL   // 12582912.0f = 1.5*2^23
#define LN2_2_C  0x3F3172183F317218ULL   // ln(2)
#define NEG1_2_C 0xBF800000BF800000ULL   // -1.0f
#define C4_2_C   0x3D2AAAAB3D2AAAABULL   // 1/24
#define C3_2_C   0x3E2AAAAB3E2AAAABULL   // 1/6
#define HALF2_C  0x3F0000003F000000ULL   // 0.5f
#define ONE2_C   0x3F8000003F800000ULL   // 1.0f

// Packed epilogue for an element pair:
//   m = ap*Mg + l; em = m+EPS; sm = em^-alpha; base = x*sm+delta;
//   out = 2^(r*lg2(base)) - delta_r  (deg-4 packed exp poly, scalar MUFU lg2/ex2)
__device__ __forceinline__ void pcen_pair(
    u64 x2, u64 l2, u64 ap2, u64 Mg2,
    u64 nalpha2, u64 r2, u64 delta2, float delta_r,
    float& ou, float& ov)
{
    u64 m2  = fma2(ap2, Mg2, l2);
    u64 em2 = add2(m2, EPS2_C);
    float emu, emv; upk2(em2, emu, emv);
    u64 t2  = mul2(pk2(fast_lg2(emu), fast_lg2(emv)), nalpha2);
    float tu, tv; upk2(t2, tu, tv);
    u64 base2 = fma2(x2, pk2(fast_ex2(tu), fast_ex2(tv)), delta2);
    float bu, bv; upk2(base2, bu, bv);
    u64 v2  = mul2(pk2(fast_lg2(bu), fast_lg2(bv)), r2);
    u64 fl2 = add2(v2, MAGIC2_C);
    u64 td2 = add2(v2, fma2(fl2, NEG1_2_C, MAGIC2_C));   // v - (fl - magic)
    u64 u2  = mul2(td2, LN2_2_C);
    u64 p2  = fma2(u2, C4_2_C, C3_2_C);
    p2 = fma2(p2, u2, HALF2_C);
    p2 = fma2(p2, u2, ONE2_C);
    p2 = fma2(p2, u2, ONE2_C);
    uint32_t flu, flv;
    asm("mov.b64 {%0, %1}, %2;" : "=r"(flu), "=r"(flv) : "l"(fl2));
    float pu, pv; upk2(p2, pu, pv);
    ou = __int_as_float(__float_as_int(pu) + ((int)flu << 23)) - delta_r;
    ov = __int_as_float(__float_as_int(pv) + ((int)flv << 23)) - delta_r;
}

__global__ __launch_bounds__(128) void pcen_kernel(
    const float* __restrict__ x,
    const float* __restrict__ s_log,
    const float* __restrict__ alpha_log,
    const float* __restrict__ delta_log,
    const float* __restrict__ r_log,
    float* __restrict__ out,
    int F, int BF)
{
    const int gwarp = (blockIdx.x * blockDim.x + threadIdx.x) >> 5;
    const int lane  = threadIdx.x & 31;
    if (gwarp >= BF * NPAIR) return;

    const int row  = gwarp / NPAIR;
    const int pair = gwarp % NPAIR;
    const int i0   = pair * CPW;

    const int b = row / F;
    const int f = row % F;

    const float alpha = __expf(alpha_log[f]);
    const float delta = __expf(delta_log[f]);
    const float r     = __expf(r_log[f]);
    const float delta_r = fast_ex2(r * fast_lg2(delta));

    const u64 nalpha2 = pk2(-alpha, -alpha);
    const u64 r2      = pk2(r, r);
    const u64 delta2  = pk2(delta, delta);

    const float4* __restrict__ xp4 = (const float4*)(x + (size_t)row * TT);
    float* __restrict__ op = out + (((size_t)b * NS + i0) * F + f) * (size_t)TT;
    const size_t s_stride = (size_t)F * TT;

    // persistent per-chain state: 8 regs per chain
    float sv[CPW], a1[CPW], a2[CPW], a4[CPW], a8[CPW], a16[CPW];
    float a16lane[CPW], carry[CPW];

    const float x0 = ((const float*)xp4)[0];

    #pragma unroll
    for (int c = 0; c < CPW; c++) {
        const float s = __expf(s_log[i0 + c]);
        sv[c] = s;
        const float a = 1.0f - s;
        a1[c]  = a;
        a2[c]  = a * a;
        a4[c]  = a2[c] * a2[c];
        a8[c]  = a4[c] * a4[c];
        a16[c] = a8[c] * a8[c];
        const float a32  = a16[c] * a16[c];
        const float a64  = a32 * a32;
        const float a128 = a64 * a64;
        const float a256 = a128 * a128;
        float ap = 1.0f;                        // (a^16)^lane
        if (lane & 1)  ap *= a16[c];
        if (lane & 2)  ap *= a32;
        if (lane & 4)  ap *= a64;
        if (lane & 8)  ap *= a128;
        if (lane & 16) ap *= a256;
        a16lane[c] = ap;
        carry[c] = x0;   // m_{-1} = x0 -> m_0 = x0 (reference init)
    }

    for (int ch = 0; ch < NCHUNK; ch++) {
        // lane owns t in [ch*512 + lane*16, +16): four float4 loads
        const int base4 = ch * 128 + lane * 4;
        const float4 xa = xp4[base4];
        const float4 xb = xp4[base4 + 1];
        const float4 xc = xp4[base4 + 2];
        const float4 xd = xp4[base4 + 3];

        #pragma unroll
        for (int c = 0; c < CPW; c++) {
            const float s = sv[c];
            const float a = a1[c];
            // local serial IIR (zero init), 16 steps
            const float l0  = s * xa.x;
            const float l1  = fmaf(a, l0,  s * xa.y);
            const float l2  = fmaf(a, l1,  s * xa.z);
            const float l3  = fmaf(a, l2,  s * xa.w);
            const float l4  = fmaf(a, l3,  s * xb.x);
            const float l5  = fmaf(a, l4,  s * xb.y);
            const float l6  = fmaf(a, l5,  s * xb.z);
            const float l7  = fmaf(a, l6,  s * xb.w);
            const float l8  = fmaf(a, l7,  s * xc.x);
            const float l9  = fmaf(a, l8,  s * xc.y);
            const float l10 = fmaf(a, l9,  s * xc.z);
            const float l11 = fmaf(a, l10, s * xc.w);
            const float l12 = fmaf(a, l11, s * xd.x);
            const float l13 = fmaf(a, l12, s * xd.y);
            const float l14 = fmaf(a, l13, s * xd.z);
            const float l15 = fmaf(a, l14, s * xd.w);

            // recompute scan ratios
            const float a32  = a16[c] * a16[c];
            const float a64  = a32 * a32;
            const float a128 = a64 * a64;
            const float a256 = a128 * a128;

            // Kogge-Stone over lane aggregates (ratio a^16)
            float S = l15;
            float v;
            v = __shfl_up_sync(0xFFFFFFFFu, S, 1);  if (lane >= 1)  S = fmaf(a16[c], v, S);
            v = __shfl_up_sync(0xFFFFFFFFu, S, 2);  if (lane >= 2)  S = fmaf(a32,    v, S);
            v = __shfl_up_sync(0xFFFFFFFFu, S, 4);  if (lane >= 4)  S = fmaf(a64,    v, S);
            v = __shfl_up_sync(0xFFFFFFFFu, S, 8);  if (lane >= 8)  S = fmaf(a128,   v, S);
            v = __shfl_up_sync(0xFFFFFFFFu, S, 16); if (lane >= 16) S = fmaf(a256,   v, S);

            const float P = __shfl_up_sync(0xFFFFFFFFu, S, 1);
            const float Mg = (lane == 0) ? carry[c]
                                         : fmaf(a16lane[c], carry[c], P);
            const float S31 = __shfl_sync(0xFFFFFFFFu, S, 31);
            carry[c] = fmaf(a256 * a256, carry[c], S31);

            const u64 Mg2 = pk2(Mg, Mg);
            // fold coefficients a^1..a^16 (recomputed, fma pipe)
            const float a3  = a1[c] * a2[c];
            const float a5  = a1[c] * a4[c];
            const float a6  = a2[c] * a4[c];
            const float a7  = a3 * a4[c];
            const float a9  = a1[c] * a8[c];
            const float a10 = a2[c] * a8[c];
            const float a11 = a3 * a8[c];
            const float a12 = a4[c] * a8[c];
            const float a13 = a5 * a8[c];
            const float a14 = a6 * a8[c];
            const float a15 = a7 * a8[c];

            float* o = op + (size_t)c * s_stride + (size_t)ch * CHUNK + lane * RPT;

            {
                float4 oa;
                pcen_pair(pk2(xa.x, xa.y), pk2(l0, l1), pk2(a1[c], a2[c]), Mg2,
                          nalpha2, r2, delta2, delta_r, oa.x, oa.y);
                pcen_pair(pk2(xa.z, xa.w), pk2(l2, l3), pk2(a3, a4[c]), Mg2,
                          nalpha2, r2, delta2, delta_r, oa.z, oa.w);
                *(float4*)o = oa;
            }
            {
                float4 ob;
                pcen_pair(pk2(xb.x, xb.y), pk2(l4, l5), pk2(a5, a6), Mg2,
                          nalpha2, r2, delta2, delta_r, ob.x, ob.y);
                pcen_pair(pk2(xb.z, xb.w), pk2(l6, l7), pk2(a7, a8[c]), Mg2,
                          nalpha2, r2, delta2, delta_r, ob.z, ob.w);
                *(float4*)(o + 4) = ob;
            }
            {
                float4 oc;
                pcen_pair(pk2(xc.x, xc.y), pk2(l8, l9), pk2(a9, a10), Mg2,
                          nalpha2, r2, delta2, delta_r, oc.x, oc.y);
                pcen_pair(pk2(xc.z, xc.w), pk2(l10, l11), pk2(a11, a12), Mg2,
                          nalpha2, r2, delta2, delta_r, oc.z, oc.w);
                *(float4*)(o + 8) = oc;
            }
            {
                float4 od;
                pcen_pair(pk2(xd.x, xd.y), pk2(l12, l13), pk2(a13, a14), Mg2,
                          nalpha2, r2, delta2, delta_r, od.x, od.y);
                pcen_pair(pk2(xd.z, xd.w), pk2(l14, l15), pk2(a15, a16[c]), Mg2,
                          nalpha2, r2, delta2, delta_r, od.z, od.w);
                *(float4*)(o + 12) = od;
            }
        }
    }
}

extern "C" void kernel_launch(void* const* d_in, const int* in_sizes, int n_in,
                              void* d_out, int out_size)
{
    const float* x         = (const float*)d_in[0];
    const float* s_log     = (const float*)d_in[1];
    const float* alpha_log = (const float*)d_in[2];
    const float* delta_log = (const float*)d_in[3];
    const float* r_log     = (const float*)d_in[4];
    float* out = (float*)d_out;

    const int F  = in_sizes[2];
    const int BF = in_sizes[0] / TT;

    const int total_warps = BF * NPAIR;
    const int threads = 128;
    const int warps_per_block = threads / 32;
    const int blocks = (total_warps + warps_per_block - 1) / warps_per_block;

    pcen_kernel<<<blocks, threads>>>(x, s_log, alpha_log, delta_log, r_log,
                                     out, F, BF);
}

// round 15
// speedup vs baseline: 1.1045x; 1.1045x over previous
#include <cuda_runtime.h>
#include <cuda_bf16.h>
#include <cstdint>

// PCEN, 10 smoother coefficients.
//   m[s,t] = (1-s)*m[s,t-1] + s*x[t],  m[s,0] = x[0]
//   out = (x*(EPS+m)^(-alpha) + delta)^r - delta^r
//
// R15: R13 (RPT=8, CPW=2, warp Kogge-Stone, packed f32x2 epilogue) with the
// middle exp2 (sm = 2^(-alpha*lg2(em))) ALSO converted to a packed poly:
// its input t2 is already packed, so 2 scalar MUFU per pair become ~7 packed
// fma + ~5 alu. MUFU drops 3 -> 2 per element (XU floor 33 -> 22 us).

#define PCEN_EPS 1e-5f
#define NS 10
#define CPW 2
#define NPAIR (NS / CPW)
#define TT 2048
#define RPT 8
#define CHUNK (32 * RPT)          // 256
#define NCHUNK (TT / CHUNK)       // 8

typedef unsigned long long u64;

__device__ __forceinline__ float fast_ex2(float v) {
    float r; asm("ex2.approx.ftz.f32 %0, %1;" : "=f"(r) : "f"(v)); return r;
}
__device__ __forceinline__ float fast_lg2(float v) {
    float r; asm("lg2.approx.ftz.f32 %0, %1;" : "=f"(r) : "f"(v)); return r;
}

// ---- f32x2 packed helpers ----
__device__ __forceinline__ u64 pk2(float lo, float hi) {
    u64 d;
    asm("mov.b64 %0, {%1, %2};" : "=l"(d)
        : "r"(__float_as_uint(lo)), "r"(__float_as_uint(hi)));
    return d;
}
__device__ __forceinline__ void upk2(u64 v, float& lo, float& hi) {
    uint32_t a, b;
    asm("mov.b64 {%0, %1}, %2;" : "=r"(a), "=r"(b) : "l"(v));
    lo = __uint_as_float(a); hi = __uint_as_float(b);
}
__device__ __forceinline__ void upk2i(u64 v, uint32_t& a, uint32_t& b) {
    asm("mov.b64 {%0, %1}, %2;" : "=r"(a), "=r"(b) : "l"(v));
}
__device__ __forceinline__ u64 fma2(u64 a, u64 b, u64 c) {
    u64 d; asm("fma.rn.f32x2 %0, %1, %2, %3;" : "=l"(d) : "l"(a), "l"(b), "l"(c)); return d;
}
__device__ __forceinline__ u64 mul2(u64 a, u64 b) {
    u64 d; asm("mul.rn.f32x2 %0, %1, %2;" : "=l"(d) : "l"(a), "l"(b)); return d;
}
__device__ __forceinline__ u64 add2(u64 a, u64 b) {
    u64 d; asm("add.rn.f32x2 %0, %1, %2;" : "=l"(d) : "l"(a), "l"(b)); return d;
}

// packed-constant bit patterns
#define EPS2_C   0x3727C5AC3727C5ACULL   // 1e-5f
#define MAGIC2_C 0x4B4000004B400000ULL   // 12582912.0f = 1.5*2^23
#define LN2_2_C  0x3F3172183F317218ULL   // ln(2)
#define NEG1_2_C 0xBF800000BF800000ULL   // -1.0f
#define C4_2_C   0x3D2AAAAB3D2AAAABULL   // 1/24
#define C3_2_C   0x3E2AAAAB3E2AAAABULL   // 1/6
#define HALF2_C  0x3F0000003F000000ULL   // 0.5f
#define ONE2_C   0x3F8000003F800000ULL   // 1.0f

// packed exp2: deg-4 poly + per-half exponent insert. |v| < ~126.
__device__ __forceinline__ u64 pexp2(u64 v2) {
    u64 fl2 = add2(v2, MAGIC2_C);
    u64 td2 = add2(v2, fma2(fl2, NEG1_2_C, MAGIC2_C));   // v - (fl - magic)
    u64 u2  = mul2(td2, LN2_2_C);
    u64 p2  = fma2(u2, C4_2_C, C3_2_C);
    p2 = fma2(p2, u2, HALF2_C);
    p2 = fma2(p2, u2, ONE2_C);
    p2 = fma2(p2, u2, ONE2_C);
    uint32_t flu, flv, pu, pv;
    upk2i(fl2, flu, flv);
    upk2i(p2, pu, pv);
    const uint32_t ru = pu + (flu << 23);
    const uint32_t rv = pv + (flv << 23);
    u64 d;
    asm("mov.b64 %0, {%1, %2};" : "=l"(d) : "r"(ru), "r"(rv));
    return d;
}

// Packed epilogue for an element pair:
//   m = ap*Mg + l; em = m+EPS; sm = em^-alpha (packed exp poly);
//   base = x*sm+delta; out = 2^(r*lg2(base)) - delta_r (packed exp poly)
// MUFU: 2 lg2 per element.
__device__ __forceinline__ void pcen_pair(
    u64 x2, u64 l2, u64 ap2, u64 Mg2,
    u64 nalpha2, u64 r2, u64 delta2, float delta_r,
    float& ou, float& ov)
{
    u64 m2  = fma2(ap2, Mg2, l2);
    u64 em2 = add2(m2, EPS2_C);
    float emu, emv; upk2(em2, emu, emv);
    u64 t2  = mul2(pk2(fast_lg2(emu), fast_lg2(emv)), nalpha2);
    u64 sm2 = pexp2(t2);                       // packed: no MUFU
    u64 base2 = fma2(x2, sm2, delta2);
    float bu, bv; upk2(base2, bu, bv);
    u64 v2  = mul2(pk2(fast_lg2(bu), fast_lg2(bv)), r2);
    u64 o2  = pexp2(v2);                       // packed: no MUFU
    float pu, pv; upk2(o2, pu, pv);
    ou = pu - delta_r;
    ov = pv - delta_r;
}

__global__ __launch_bounds__(128) void pcen_kernel(
    const float* __restrict__ x,
    const float* __restrict__ s_log,
    const float* __restrict__ alpha_log,
    const float* __restrict__ delta_log,
    const float* __restrict__ r_log,
    float* __restrict__ out,
    int F, int BF)
{
    const int gwarp = (blockIdx.x * blockDim.x + threadIdx.x) >> 5;
    const int lane  = threadIdx.x & 31;
    if (gwarp >= BF * NPAIR) return;

    const int row  = gwarp / NPAIR;
    const int pair = gwarp % NPAIR;
    const int i0   = pair * CPW;

    const int b = row / F;
    const int f = row % F;

    const float alpha = __expf(alpha_log[f]);
    const float delta = __expf(delta_log[f]);
    const float r     = __expf(r_log[f]);
    const float delta_r = fast_ex2(r * fast_lg2(delta));

    const u64 nalpha2 = pk2(-alpha, -alpha);
    const u64 r2      = pk2(r, r);
    const u64 delta2  = pk2(delta, delta);

    const float4* __restrict__ xp4 = (const float4*)(x + (size_t)row * TT);
    float* __restrict__ op = out + (((size_t)b * NS + i0) * F + f) * (size_t)TT;
    const size_t s_stride = (size_t)F * TT;

    // persistent per-chain state: 7 regs per chain
    float sv[CPW], a1[CPW], a2[CPW], a4[CPW], a8[CPW];
    float a8lane[CPW], carry[CPW];

    const float x0 = ((const float*)xp4)[0];

    #pragma unroll
    for (int c = 0; c < CPW; c++) {
        const float s = __expf(s_log[i0 + c]);
        sv[c] = s;
        const float a = 1.0f - s;
        a1[c] = a;
        a2[c] = a * a;
        a4[c] = a2[c] * a2[c];
        a8[c] = a4[c] * a4[c];
        const float a16  = a8[c] * a8[c];
        const float a32  = a16 * a16;
        const float a64  = a32 * a32;
        const float a128 = a64 * a64;
        float ap = 1.0f;                        // (a^8)^lane
        if (lane & 1)  ap *= a8[c];
        if (lane & 2)  ap *= a16;
        if (lane & 4)  ap *= a32;
        if (lane & 8)  ap *= a64;
        if (lane & 16) ap *= a128;
        a8lane[c] = ap;
        carry[c] = x0;   // m_{-1} = x0 -> m_0 = x0 (reference init)
    }

    for (int ch = 0; ch < NCHUNK; ch++) {
        // lane owns t in [ch*256 + lane*8, +8): two float4 loads
        const int base4 = ch * 64 + lane * 2;
        const float4 xa = xp4[base4];
        const float4 xb = xp4[base4 + 1];

        // packed x pairs, shared by both chains
        const u64 x01 = pk2(xa.x, xa.y);
        const u64 x23 = pk2(xa.z, xa.w);
        const u64 x45 = pk2(xb.x, xb.y);
        const u64 x67 = pk2(xb.z, xb.w);

        #pragma unroll
        for (int c = 0; c < CPW; c++) {
            const float s = sv[c];
            const float a = a1[c];
            // local serial IIR (zero init), 8 steps
            const float l0 = s * xa.x;
            const float l1 = fmaf(a, l0, s * xa.y);
            const float l2 = fmaf(a, l1, s * xa.z);
            const float l3 = fmaf(a, l2, s * xa.w);
            const float l4 = fmaf(a, l3, s * xb.x);
            const float l5 = fmaf(a, l4, s * xb.y);
            const float l6 = fmaf(a, l5, s * xb.z);
            const float l7 = fmaf(a, l6, s * xb.w);

            // recompute scan ratios (cheap)
            const float a16  = a8[c] * a8[c];
            const float a32  = a16 * a16;
            const float a64  = a32 * a32;
            const float a128 = a64 * a64;

            // Kogge-Stone over lane aggregates (ratio a^8)
            float S = l7;
            float v;
            v = __shfl_up_sync(0xFFFFFFFFu, S, 1);  if (lane >= 1)  S = fmaf(a8[c], v, S);
            v = __shfl_up_sync(0xFFFFFFFFu, S, 2);  if (lane >= 2)  S = fmaf(a16,   v, S);
            v = __shfl_up_sync(0xFFFFFFFFu, S, 4);  if (lane >= 4)  S = fmaf(a32,   v, S);
            v = __shfl_up_sync(0xFFFFFFFFu, S, 8);  if (lane >= 8)  S = fmaf(a64,   v, S);
            v = __shfl_up_sync(0xFFFFFFFFu, S, 16); if (lane >= 16) S = fmaf(a128,  v, S);

            const float P = __shfl_up_sync(0xFFFFFFFFu, S, 1);
            const float Mg = (lane == 0) ? carry[c]
                                         : fmaf(a8lane[c], carry[c], P);
            const float S31 = __shfl_sync(0xFFFFFFFFu, S, 31);
            carry[c] = fmaf(a128 * a128, carry[c], S31);

            const u64 Mg2 = pk2(Mg, Mg);
            const float a3 = a1[c] * a2[c];
            const float a5 = a1[c] * a4[c];
            const float a6 = a2[c] * a4[c];
            const float a7 = a3 * a4[c];

            float* o = op + (size_t)c * s_stride + (size_t)ch * CHUNK + lane * RPT;

            // first half: elements 0..3 (two packed pairs), store
            {
                float4 oa;
                pcen_pair(x01, pk2(l0, l1), pk2(a1[c], a2[c]), Mg2,
                          nalpha2, r2, delta2, delta_r, oa.x, oa.y);
                pcen_pair(x23, pk2(l2, l3), pk2(a3, a4[c]), Mg2,
                          nalpha2, r2, delta2, delta_r, oa.z, oa.w);
                *(float4*)o = oa;
            }
            // second half: elements 4..7, store
            {
                float4 ob;
                pcen_pair(x45, pk2(l4, l5), pk2(a5, a6), Mg2,
                          nalpha2, r2, delta2, delta_r, ob.x, ob.y);
                pcen_pair(x67, pk2(l6, l7), pk2(a7, a8[c]), Mg2,
                          nalpha2, r2, delta2, delta_r, ob.z, ob.w);
                *(float4*)(o + 4) = ob;
            }
        }
    }
}

extern "C" void kernel_launch(void* const* d_in, const int* in_sizes, int n_in,
                              void* d_out, int out_size)
{
    const float* x         = (const float*)d_in[0];
    const float* s_log     = (const float*)d_in[1];
    const float* alpha_log = (const float*)d_in[2];
    const float* delta_log = (const float*)d_in[3];
    const float* r_log     = (const float*)d_in[4];
    float* out = (float*)d_out;

    const int F  = in_sizes[2];
    const int BF = in_sizes[0] / TT;

    const int total_warps = BF * NPAIR;
    const int threads = 128;
    const int warps_per_block = threads / 32;
    const int blocks = (total_warps + warps_per_block - 1) / warps_per_block;

    pcen_kernel<<<blocks, threads>>>(x, s_log, alpha_log, delta_log, r_log,
                                     out, F, BF);
}

// round 16
// speedup vs baseline: 1.1826x; 1.0707x over previous
#include <cuda_runtime.h>
#include <cuda_bf16.h>
#include <cstdint>

// PCEN, 10 smoother coefficients.
//   m[s,t] = (1-s)*m[s,t-1] + s*x[t],  m[s,0] = x[0]
//   out = (x*(EPS+m)^(-alpha) + delta)^r - delta^r
//
// R16: R13 (RPT=8, CPW=2, warp Kogge-Stone, packed f32x2 epilogue, 3 MUFU +
// 1 packed-poly exp2 per elem) with register-liveness trim: x pairs packed
// inline per pcen_pair call (not hoisted across the chain loop), mild
// __launch_bounds__(128,8) targeting 64 regs -> 32 warps/SM.

#define PCEN_EPS 1e-5f
#define NS 10
#define CPW 2
#define NPAIR (NS / CPW)
#define TT 2048
#define RPT 8
#define CHUNK (32 * RPT)          // 256
#define NCHUNK (TT / CHUNK)       // 8

typedef unsigned long long u64;

__device__ __forceinline__ float fast_ex2(float v) {
    float r; asm("ex2.approx.ftz.f32 %0, %1;" : "=f"(r) : "f"(v)); return r;
}
__device__ __forceinline__ float fast_lg2(float v) {
    float r; asm("lg2.approx.ftz.f32 %0, %1;" : "=f"(r) : "f"(v)); return r;
}

// ---- f32x2 packed helpers ----
__device__ __forceinline__ u64 pk2(float lo, float hi) {
    u64 d;
    asm("mov.b64 %0, {%1, %2};" : "=l"(d)
        : "r"(__float_as_uint(lo)), "r"(__float_as_uint(hi)));
    return d;
}
__device__ __forceinline__ void upk2(u64 v, float& lo, float& hi) {
    uint32_t a, b;
    asm("mov.b64 {%0, %1}, %2;" : "=r"(a), "=r"(b) : "l"(v));
    lo = __uint_as_float(a); hi = __uint_as_float(b);
}
__device__ __forceinline__ u64 fma2(u64 a, u64 b, u64 c) {
    u64 d; asm("fma.rn.f32x2 %0, %1, %2, %3;" : "=l"(d) : "l"(a), "l"(b), "l"(c)); return d;
}
__device__ __forceinline__ u64 mul2(u64 a, u64 b) {
    u64 d; asm("mul.rn.f32x2 %0, %1, %2;" : "=l"(d) : "l"(a), "l"(b)); return d;
}
__device__ __forceinline__ u64 add2(u64 a, u64 b) {
    u64 d; asm("add.rn.f32x2 %0, %1, %2;" : "=l"(d) : "l"(a), "l"(b)); return d;
}

// packed-constant bit patterns
#define EPS2_C   0x3727C5AC3727C5ACULL   // 1e-5f
#define MAGIC2_C 0x4B4000004B400000ULL   // 12582912.0f = 1.5*2^23
#define LN2_2_C  0x3F3172183F317218ULL   // ln(2)
#define NEG1_2_C 0xBF800000BF800000ULL   // -1.0f
#define C4_2_C   0x3D2AAAAB3D2AAAABULL   // 1/24
#define C3_2_C   0x3E2AAAAB3E2AAAABULL   // 1/6
#define HALF2_C  0x3F0000003F000000ULL   // 0.5f
#define ONE2_C   0x3F8000003F800000ULL   // 1.0f

// Packed epilogue for an element pair (R13 math: MUFU lg2/ex2/lg2, packed
// final exp2 poly):
//   m = ap*Mg + l; em = m+EPS; sm = em^-alpha; base = x*sm+delta;
//   out = 2^(r*lg2(base)) - delta_r
__device__ __forceinline__ void pcen_pair(
    float xu, float xv, float lu, float lv, float apu, float apv, float Mg,
    u64 nalpha2, u64 r2, u64 delta2, float delta_r,
    float& ou, float& ov)
{
    u64 m2  = fma2(pk2(apu, apv), pk2(Mg, Mg), pk2(lu, lv));
    u64 em2 = add2(m2, EPS2_C);
    float emu, emv; upk2(em2, emu, emv);
    u64 t2  = mul2(pk2(fast_lg2(emu), fast_lg2(emv)), nalpha2);
    float tu, tv; upk2(t2, tu, tv);
    u64 base2 = fma2(pk2(xu, xv), pk2(fast_ex2(tu), fast_ex2(tv)), delta2);
    float bu, bv; upk2(base2, bu, bv);
    u64 v2  = mul2(pk2(fast_lg2(bu), fast_lg2(bv)), r2);
    // packed exp2: magic round + deg-4 poly + scalar exponent insert
    u64 fl2 = add2(v2, MAGIC2_C);
    u64 td2 = add2(v2, fma2(fl2, NEG1_2_C, MAGIC2_C));   // v - (fl - magic)
    u64 u2  = mul2(td2, LN2_2_C);
    u64 p2  = fma2(u2, C4_2_C, C3_2_C);
    p2 = fma2(p2, u2, HALF2_C);
    p2 = fma2(p2, u2, ONE2_C);
    p2 = fma2(p2, u2, ONE2_C);
    uint32_t flu, flv;
    asm("mov.b64 {%0, %1}, %2;" : "=r"(flu), "=r"(flv) : "l"(fl2));
    float pu, pv; upk2(p2, pu, pv);
    ou = __int_as_float(__float_as_int(pu) + ((int)flu << 23)) - delta_r;
    ov = __int_as_float(__float_as_int(pv) + ((int)flv << 23)) - delta_r;
}

__global__ __launch_bounds__(128, 8) void pcen_kernel(
    const float* __restrict__ x,
    const float* __restrict__ s_log,
    const float* __restrict__ alpha_log,
    const float* __restrict__ delta_log,
    const float* __restrict__ r_log,
    float* __restrict__ out,
    int F, int BF)
{
    const int gwarp = (blockIdx.x * blockDim.x + threadIdx.x) >> 5;
    const int lane  = threadIdx.x & 31;
    if (gwarp >= BF * NPAIR) return;

    const int row  = gwarp / NPAIR;
    const int pair = gwarp % NPAIR;
    const int i0   = pair * CPW;

    const int b = row / F;
    const int f = row % F;

    const float alpha = __expf(alpha_log[f]);
    const float delta = __expf(delta_log[f]);
    const float r     = __expf(r_log[f]);
    const float delta_r = fast_ex2(r * fast_lg2(delta));

    const u64 nalpha2 = pk2(-alpha, -alpha);
    const u64 r2      = pk2(r, r);
    const u64 delta2  = pk2(delta, delta);

    const float4* __restrict__ xp4 = (const float4*)(x + (size_t)row * TT);
    float* __restrict__ op = out + (((size_t)b * NS + i0) * F + f) * (size_t)TT;
    const size_t s_stride = (size_t)F * TT;

    // persistent per-chain state: 7 regs per chain
    float sv[CPW], a1[CPW], a2[CPW], a4[CPW], a8[CPW];
    float a8lane[CPW], carry[CPW];

    const float x0 = ((const float*)xp4)[0];

    #pragma unroll
    for (int c = 0; c < CPW; c++) {
        const float s = __expf(s_log[i0 + c]);
        sv[c] = s;
        const float a = 1.0f - s;
        a1[c] = a;
        a2[c] = a * a;
        a4[c] = a2[c] * a2[c];
        a8[c] = a4[c] * a4[c];
        const float a16  = a8[c] * a8[c];
        const float a32  = a16 * a16;
        const float a64  = a32 * a32;
        const float a128 = a64 * a64;
        float ap = 1.0f;                        // (a^8)^lane
        if (lane & 1)  ap *= a8[c];
        if (lane & 2)  ap *= a16;
        if (lane & 4)  ap *= a32;
        if (lane & 8)  ap *= a64;
        if (lane & 16) ap *= a128;
        a8lane[c] = ap;
        carry[c] = x0;   // m_{-1} = x0 -> m_0 = x0 (reference init)
    }

    for (int ch = 0; ch < NCHUNK; ch++) {
        // lane owns t in [ch*256 + lane*8, +8): two float4 loads
        const int base4 = ch * 64 + lane * 2;
        const float4 xa = xp4[base4];
        const float4 xb = xp4[base4 + 1];

        #pragma unroll
        for (int c = 0; c < CPW; c++) {
            const float s = sv[c];
            const float a = a1[c];
            // local serial IIR (zero init), 8 steps
            const float l0 = s * xa.x;
            const float l1 = fmaf(a, l0, s * xa.y);
            const float l2 = fmaf(a, l1, s * xa.z);
            const float l3 = fmaf(a, l2, s * xa.w);
            const float l4 = fmaf(a, l3, s * xb.x);
            const float l5 = fmaf(a, l4, s * xb.y);
            const float l6 = fmaf(a, l5, s * xb.z);
            const float l7 = fmaf(a, l6, s * xb.w);

            // recompute scan ratios (cheap)
            const float a16  = a8[c] * a8[c];
            const float a32  = a16 * a16;
            const float a64  = a32 * a32;
            const float a128 = a64 * a64;

            // Kogge-Stone over lane aggregates (ratio a^8)
            float S = l7;
            float v;
            v = __shfl_up_sync(0xFFFFFFFFu, S, 1);  if (lane >= 1)  S = fmaf(a8[c], v, S);
            v = __shfl_up_sync(0xFFFFFFFFu, S, 2);  if (lane >= 2)  S = fmaf(a16,   v, S);
            v = __shfl_up_sync(0xFFFFFFFFu, S, 4);  if (lane >= 4)  S = fmaf(a32,   v, S);
            v = __shfl_up_sync(0xFFFFFFFFu, S, 8);  if (lane >= 8)  S = fmaf(a64,   v, S);
            v = __shfl_up_sync(0xFFFFFFFFu, S, 16); if (lane >= 16) S = fmaf(a128,  v, S);

            const float P = __shfl_up_sync(0xFFFFFFFFu, S, 1);
            const float Mg = (lane == 0) ? carry[c]
                                         : fmaf(a8lane[c], carry[c], P);
            const float S31 = __shfl_sync(0xFFFFFFFFu, S, 31);
            carry[c] = fmaf(a128 * a128, carry[c], S31);

            const float a3 = a1[c] * a2[c];
            const float a5 = a1[c] * a4[c];
            const float a6 = a2[c] * a4[c];
            const float a7 = a3 * a4[c];

            float* o = op + (size_t)c * s_stride + (size_t)ch * CHUNK + lane * RPT;

            // first half: elements 0..3 (two packed pairs), store
            {
                float4 oa;
                pcen_pair(xa.x, xa.y, l0, l1, a1[c], a2[c], Mg,
                          nalpha2, r2, delta2, delta_r, oa.x, oa.y);
                pcen_pair(xa.z, xa.w, l2, l3, a3, a4[c], Mg,
                          nalpha2, r2, delta2, delta_r, oa.z, oa.w);
                *(float4*)o = oa;
            }
            // second half: elements 4..7, store
            {
                float4 ob;
                pcen_pair(xb.x, xb.y, l4, l5, a5, a6, Mg,
                          nalpha2, r2, delta2, delta_r, ob.x, ob.y);
                pcen_pair(xb.z, xb.w, l6, l7, a7, a8[c], Mg,
                          nalpha2, r2, delta2, delta_r, ob.z, ob.w);
                *(float4*)(o + 4) = ob;
            }
        }
    }
}

extern "C" void kernel_launch(void* const* d_in, const int* in_sizes, int n_in,
                              void* d_out, int out_size)
{
    const float* x         = (const float*)d_in[0];
    const float* s_log     = (const float*)d_in[1];
    const float* alpha_log = (const float*)d_in[2];
    const float* delta_log = (const float*)d_in[3];
    const float* r_log     = (const float*)d_in[4];
    float* out = (float*)d_out;

    const int F  = in_sizes[2];
    const int BF = in_sizes[0] / TT;

    const int total_warps = BF * NPAIR;
    const int threads = 128;
    const int warps_per_block = threads / 32;
    const int blocks = (total_warps + warps_per_block - 1) / warps_per_block;

    pcen_kernel<<<blocks, threads>>>(x, s_log, alpha_log, delta_log, r_log,
                                     out, F, BF);
}

// round 17
// speedup vs baseline: 1.2032x; 1.0175x over previous
#include <cuda_runtime.h>
#include <cuda_bf16.h>
#include <cstdint>

// PCEN, 10 smoother coefficients.
//   m[s,t] = (1-s)*m[s,t-1] + s*x[t],  m[s,0] = x[0]
//   out = (x*(EPS+m)^(-alpha) + delta)^r - delta^r
//
// R17: R13 (best: RPT=8, CPW=2, warp Kogge-Stone, packed f32x2 epilogue,
// 3 MUFU + 1 packed-poly exp2) + one-deep load prefetch: chunk ch+1's two
// float4 loads issue before chunk ch's compute, hiding the 234-577cy
// global-load latency that was exposed at the top of every chunk.

#define PCEN_EPS 1e-5f
#define NS 10
#define CPW 2
#define NPAIR (NS / CPW)
#define TT 2048
#define RPT 8
#define CHUNK (32 * RPT)          // 256
#define NCHUNK (TT / CHUNK)       // 8

typedef unsigned long long u64;

__device__ __forceinline__ float fast_ex2(float v) {
    float r; asm("ex2.approx.ftz.f32 %0, %1;" : "=f"(r) : "f"(v)); return r;
}
__device__ __forceinline__ float fast_lg2(float v) {
    float r; asm("lg2.approx.ftz.f32 %0, %1;" : "=f"(r) : "f"(v)); return r;
}

// ---- f32x2 packed helpers ----
__device__ __forceinline__ u64 pk2(float lo, float hi) {
    u64 d;
    asm("mov.b64 %0, {%1, %2};" : "=l"(d)
        : "r"(__float_as_uint(lo)), "r"(__float_as_uint(hi)));
    return d;
}
__device__ __forceinline__ void upk2(u64 v, float& lo, float& hi) {
    uint32_t a, b;
    asm("mov.b64 {%0, %1}, %2;" : "=r"(a), "=r"(b) : "l"(v));
    lo = __uint_as_float(a); hi = __uint_as_float(b);
}
__device__ __forceinline__ u64 fma2(u64 a, u64 b, u64 c) {
    u64 d; asm("fma.rn.f32x2 %0, %1, %2, %3;" : "=l"(d) : "l"(a), "l"(b), "l"(c)); return d;
}
__device__ __forceinline__ u64 mul2(u64 a, u64 b) {
    u64 d; asm("mul.rn.f32x2 %0, %1, %2;" : "=l"(d) : "l"(a), "l"(b)); return d;
}
__device__ __forceinline__ u64 add2(u64 a, u64 b) {
    u64 d; asm("add.rn.f32x2 %0, %1, %2;" : "=l"(d) : "l"(a), "l"(b)); return d;
}

// packed-constant bit patterns
#define EPS2_C   0x3727C5AC3727C5ACULL   // 1e-5f
#define MAGIC2_C 0x4B4000004B400000ULL   // 12582912.0f = 1.5*2^23
#define LN2_2_C  0x3F3172183F317218ULL   // ln(2)
#define NEG1_2_C 0xBF800000BF800000ULL   // -1.0f
#define C4_2_C   0x3D2AAAAB3D2AAAABULL   // 1/24
#define C3_2_C   0x3E2AAAAB3E2AAAABULL   // 1/6
#define HALF2_C  0x3F0000003F000000ULL   // 0.5f
#define ONE2_C   0x3F8000003F800000ULL   // 1.0f

// Packed epilogue for an element pair:
//   m = ap*Mg + l; em = m+EPS; sm = em^-alpha; base = x*sm+delta;
//   out = 2^(r*lg2(base)) - delta_r   (deg-4 packed exp poly)
__device__ __forceinline__ void pcen_pair(
    u64 x2, u64 l2, u64 ap2, u64 Mg2,
    u64 nalpha2, u64 r2, u64 delta2, float delta_r,
    float& ou, float& ov)
{
    u64 m2  = fma2(ap2, Mg2, l2);
    u64 em2 = add2(m2, EPS2_C);
    float emu, emv; upk2(em2, emu, emv);
    u64 t2  = mul2(pk2(fast_lg2(emu), fast_lg2(emv)), nalpha2);
    float tu, tv; upk2(t2, tu, tv);
    u64 base2 = fma2(x2, pk2(fast_ex2(tu), fast_ex2(tv)), delta2);
    float bu, bv; upk2(base2, bu, bv);
    u64 v2  = mul2(pk2(fast_lg2(bu), fast_lg2(bv)), r2);
    u64 fl2 = add2(v2, MAGIC2_C);
    u64 td2 = add2(v2, fma2(fl2, NEG1_2_C, MAGIC2_C));   // v - (fl - magic)
    u64 u2  = mul2(td2, LN2_2_C);
    u64 p2  = fma2(u2, C4_2_C, C3_2_C);
    p2 = fma2(p2, u2, HALF2_C);
    p2 = fma2(p2, u2, ONE2_C);
    p2 = fma2(p2, u2, ONE2_C);
    uint32_t flu, flv;
    asm("mov.b64 {%0, %1}, %2;" : "=r"(flu), "=r"(flv) : "l"(fl2));
    float pu, pv; upk2(p2, pu, pv);
    ou = __int_as_float(__float_as_int(pu) + ((int)flu << 23)) - delta_r;
    ov = __int_as_float(__float_as_int(pv) + ((int)flv << 23)) - delta_r;
}

__global__ __launch_bounds__(128) void pcen_kernel(
    const float* __restrict__ x,
    const float* __restrict__ s_log,
    const float* __restrict__ alpha_log,
    const float* __restrict__ delta_log,
    const float* __restrict__ r_log,
    float* __restrict__ out,
    int F, int BF)
{
    const int gwarp = (blockIdx.x * blockDim.x + threadIdx.x) >> 5;
    const int lane  = threadIdx.x & 31;
    if (gwarp >= BF * NPAIR) return;

    const int row  = gwarp / NPAIR;
    const int pair = gwarp % NPAIR;
    const int i0   = pair * CPW;

    const int b = row / F;
    const int f = row % F;

    const float alpha = __expf(alpha_log[f]);
    const float delta = __expf(delta_log[f]);
    const float r     = __expf(r_log[f]);
    const float delta_r = fast_ex2(r * fast_lg2(delta));

    const u64 nalpha2 = pk2(-alpha, -alpha);
    const u64 r2      = pk2(r, r);
    const u64 delta2  = pk2(delta, delta);

    const float4* __restrict__ xp4 = (const float4*)(x + (size_t)row * TT);
    float* __restrict__ op = out + (((size_t)b * NS + i0) * F + f) * (size_t)TT;
    const size_t s_stride = (size_t)F * TT;

    // persistent per-chain state: 7 regs per chain
    float sv[CPW], a1[CPW], a2[CPW], a4[CPW], a8[CPW];
    float a8lane[CPW], carry[CPW];

    const float x0 = ((const float*)xp4)[0];

    #pragma unroll
    for (int c = 0; c < CPW; c++) {
        const float s = __expf(s_log[i0 + c]);
        sv[c] = s;
        const float a = 1.0f - s;
        a1[c] = a;
        a2[c] = a * a;
        a4[c] = a2[c] * a2[c];
        a8[c] = a4[c] * a4[c];
        const float a16  = a8[c] * a8[c];
        const float a32  = a16 * a16;
        const float a64  = a32 * a32;
        const float a128 = a64 * a64;
        float ap = 1.0f;                        // (a^8)^lane
        if (lane & 1)  ap *= a8[c];
        if (lane & 2)  ap *= a16;
        if (lane & 4)  ap *= a32;
        if (lane & 8)  ap *= a64;
        if (lane & 16) ap *= a128;
        a8lane[c] = ap;
        carry[c] = x0;   // m_{-1} = x0 -> m_0 = x0 (reference init)
    }

    // ---- load pipeline: prefetch chunk 0 ----
    float4 xa = xp4[lane * 2];
    float4 xb = xp4[lane * 2 + 1];

    #pragma unroll 1
    for (int ch = 0; ch < NCHUNK; ch++) {
        // issue next chunk's loads FIRST (clamped index; harmless reread on last)
        const int nch = (ch + 1 < NCHUNK) ? (ch + 1) : ch;
        const int nbase4 = nch * 64 + lane * 2;
        const float4 nxa = xp4[nbase4];
        const float4 nxb = xp4[nbase4 + 1];

        // packed x pairs for this chunk, shared by both chains
        const u64 x01 = pk2(xa.x, xa.y);
        const u64 x23 = pk2(xa.z, xa.w);
        const u64 x45 = pk2(xb.x, xb.y);
        const u64 x67 = pk2(xb.z, xb.w);

        #pragma unroll
        for (int c = 0; c < CPW; c++) {
            const float s = sv[c];
            const float a = a1[c];
            // local serial IIR (zero init), 8 steps
            const float l0 = s * xa.x;
            const float l1 = fmaf(a, l0, s * xa.y);
            const float l2 = fmaf(a, l1, s * xa.z);
            const float l3 = fmaf(a, l2, s * xa.w);
            const float l4 = fmaf(a, l3, s * xb.x);
            const float l5 = fmaf(a, l4, s * xb.y);
            const float l6 = fmaf(a, l5, s * xb.z);
            const float l7 = fmaf(a, l6, s * xb.w);

            // recompute scan ratios (cheap)
            const float a16  = a8[c] * a8[c];
            const float a32  = a16 * a16;
            const float a64  = a32 * a32;
            const float a128 = a64 * a64;

            // Kogge-Stone over lane aggregates (ratio a^8)
            float S = l7;
            float v;
            v = __shfl_up_sync(0xFFFFFFFFu, S, 1);  if (lane >= 1)  S = fmaf(a8[c], v, S);
            v = __shfl_up_sync(0xFFFFFFFFu, S, 2);  if (lane >= 2)  S = fmaf(a16,   v, S);
            v = __shfl_up_sync(0xFFFFFFFFu, S, 4);  if (lane >= 4)  S = fmaf(a32,   v, S);
            v = __shfl_up_sync(0xFFFFFFFFu, S, 8);  if (lane >= 8)  S = fmaf(a64,   v, S);
            v = __shfl_up_sync(0xFFFFFFFFu, S, 16); if (lane >= 16) S = fmaf(a128,  v, S);

            const float P = __shfl_up_sync(0xFFFFFFFFu, S, 1);
            const float Mg = (lane == 0) ? carry[c]
                                         : fmaf(a8lane[c], carry[c], P);
            const float S31 = __shfl_sync(0xFFFFFFFFu, S, 31);
            carry[c] = fmaf(a128 * a128, carry[c], S31);

            const u64 Mg2 = pk2(Mg, Mg);
            const float a3 = a1[c] * a2[c];
            const float a5 = a1[c] * a4[c];
            const float a6 = a2[c] * a4[c];
            const float a7 = a3 * a4[c];

            float* o = op + (size_t)c * s_stride + (size_t)ch * CHUNK + lane * RPT;

            // first half: elements 0..3 (two packed pairs), store
            {
                float4 oa;
                pcen_pair(x01, pk2(l0, l1), pk2(a1[c], a2[c]), Mg2,
                          nalpha2, r2, delta2, delta_r, oa.x, oa.y);
                pcen_pair(x23, pk2(l2, l3), pk2(a3, a4[c]), Mg2,
                          nalpha2, r2, delta2, delta_r, oa.z, oa.w);
                *(float4*)o = oa;
            }
            // second half: elements 4..7, store
            {
                float4 ob;
                pcen_pair(x45, pk2(l4, l5), pk2(a5, a6), Mg2,
                          nalpha2, r2, delta2, delta_r, ob.x, ob.y);
                pcen_pair(x67, pk2(l6, l7), pk2(a7, a8[c]), Mg2,
                          nalpha2, r2, delta2, delta_r, ob.z, ob.w);
                *(float4*)(o + 4) = ob;
            }
        }

        xa = nxa; xb = nxb;
    }
}

extern "C" void kernel_launch(void* const* d_in, const int* in_sizes, int n_in,
                              void* d_out, int out_size)
{
    const float* x         = (const float*)d_in[0];
    const float* s_log     = (const float*)d_in[1];
    const float* alpha_log = (const float*)d_in[2];
    const float* delta_log = (const float*)d_in[3];
    const float* r_log     = (const float*)d_in[4];
    float* out = (float*)d_out;

    const int F  = in_sizes[2];
    const int BF = in_sizes[0] / TT;

    const int total_warps = BF * NPAIR;
    const int threads = 128;
    const int warps_per_block = threads / 32;
    const int blocks = (total_warps + warps_per_block - 1) / warps_per_block;

    pcen_kernel<<<blocks, threads>>>(x, s_log, alpha_log, delta_log, r_log,
                                     out, F, BF);
}